// round 7
// baseline (speedup 1.0000x reference)
#include <cuda_runtime.h>
#include <cstddef>
#include <cstdint>

// Problem constants (from reference)
static constexpr int B  = 4;
static constexpr int C  = 64;
static constexpr int NX = 432;
static constexpr int NY = 496;
static constexpr int NBINS = 3;
static constexpr int  PLANE   = NY * NX;            // 214272
static constexpr int  PLANE4  = PLANE / 4;          // 53568
static constexpr long PER_BIN4 = (long)B * C * PLANE4;

// Inverse index map: cell -> pillar row + 1 (0 = empty). uint16 (np<65535).
// INVARIANT: all-zero at kernel_launch entry. Zero-initialized at module
// load; the gather kernel re-zeroes every entry it found occupied, restoring
// the invariant for the next call (including graph replays).
__device__ unsigned short g_idx[NBINS * B * PLANE];

// ---------------------------------------------------------------------------
// Kernel 1: scatter (pillar row + 1) into the map. Flat grid over all
// 3*np pillars (tiny: 192K threads, one 16B coord load + one 2B store each).
// ---------------------------------------------------------------------------
__global__ void scatter_idx(const int* __restrict__ vc0,
                            const int* __restrict__ vc1,
                            const int* __restrict__ vc2, int np) {
    int t = blockIdx.x * blockDim.x + threadIdx.x;
    if (t >= NBINS * np) return;
    int bin = t / np;
    int p   = t - bin * np;
    const int* vc = (bin == 0) ? vc0 : (bin == 1) ? vc1 : vc2;
    int4 co = reinterpret_cast<const int4*>(vc)[p];  // [b, z, y, x]
    // reference flat-in-sample: z + y*NX + x (z == 0, kept for exactness)
    int cell = co.x * PLANE + co.y + co.z * NX + co.w;
    g_idx[bin * (B * PLANE) + cell] = (unsigned short)(p + 1);
}

// ---------------------------------------------------------------------------
// Kernel 2: streaming gather + self-clearing map.
// Thread owns 4 consecutive cells: one ushort4 idx load (then zeroes the
// entry if occupied). Channel loop: 4 channels/iter, one LDG.128 per
// occupied cell, register transpose, 4 coalesced float4 streaming stores.
// unroll 1 + launch_bounds(256,6) keep regs low so 6 blocks/SM fit ->
// more store-MLP in flight for the HBM write stream.
// grid = (ceil(PLANE4/256), B, NBINS)
// ---------------------------------------------------------------------------
__global__ void __launch_bounds__(256, 6)
gather_out(const float* __restrict__ pf0,
           const float* __restrict__ pf1,
           const float* __restrict__ pf2,
           float* __restrict__ out) {
    const int bin = blockIdx.z;
    const float* __restrict__ pf = (bin == 0) ? pf0 : (bin == 1) ? pf1 : pf2;
    const int b = blockIdx.y;

    int s4 = blockIdx.x * blockDim.x + threadIdx.x;
    if (s4 >= PLANE4) return;

    ushort4* map4 = reinterpret_cast<ushort4*>(
        g_idx + (size_t)(bin * B + b) * PLANE);
    const ushort4 u = map4[s4];

    // Self-clear: restore the all-zero invariant for the next launch.
    if (u.x | u.y | u.z | u.w) {
        map4[s4] = make_ushort4(0, 0, 0, 0);
    }

    // Feature row base pointers ((p+1-1) * 64 channels)
    const float* p0 = pf + (((int)u.x - 1) << 6);
    const float* p1 = pf + (((int)u.y - 1) << 6);
    const float* p2 = pf + (((int)u.z - 1) << 6);
    const float* p3 = pf + (((int)u.w - 1) << 6);

    float4* dst = reinterpret_cast<float4*>(out)
                + (long)bin * PER_BIN4 + (long)b * C * PLANE4 + s4;

    const float4 z4 = make_float4(0.f, 0.f, 0.f, 0.f);

    #pragma unroll 1
    for (int c = 0; c < C; c += 4) {
        // One 16B load per occupied cell: channels c..c+3 of its feature row
        float4 r0 = u.x ? __ldg(reinterpret_cast<const float4*>(p0 + c)) : z4;
        float4 r1 = u.y ? __ldg(reinterpret_cast<const float4*>(p1 + c)) : z4;
        float4 r2 = u.z ? __ldg(reinterpret_cast<const float4*>(p2 + c)) : z4;
        float4 r3 = u.w ? __ldg(reinterpret_cast<const float4*>(p3 + c)) : z4;

        // Register transpose: channel-major stores (cells 0..3 contiguous)
        __stcs(dst,              make_float4(r0.x, r1.x, r2.x, r3.x));
        __stcs(dst + PLANE4,     make_float4(r0.y, r1.y, r2.y, r3.y));
        __stcs(dst + 2 * PLANE4, make_float4(r0.z, r1.z, r2.z, r3.z));
        __stcs(dst + 3 * PLANE4, make_float4(r0.w, r1.w, r2.w, r3.w));
        dst += 4 * PLANE4;
    }
}

extern "C" void kernel_launch(void* const* d_in, const int* in_sizes, int n_in,
                              void* d_out, int out_size) {
    const float* pf0 = (const float*)d_in[0];
    const int*   vc0 = (const int*)  d_in[1];
    const float* pf1 = (const float*)d_in[2];
    const int*   vc1 = (const int*)  d_in[3];
    const float* pf2 = (const float*)d_in[4];
    const int*   vc2 = (const int*)  d_in[5];
    float* out = (float*)d_out;

    const int np = in_sizes[1] / 4;  // pillars per bin

    // 1) scatter pillar ids (+1) into the (all-zero) idx map
    {
        int total = NBINS * np;
        scatter_idx<<<(total + 255) / 256, 256>>>(vc0, vc1, vc2, np);
    }

    // 2) streaming gather -> output; also re-zeroes the map entries it used
    {
        dim3 grid((PLANE4 + 255) / 256, B, NBINS);
        gather_out<<<grid, 256>>>(pf0, pf1, pf2, out);
    }
}

// round 8
// speedup vs baseline: 1.0415x; 1.0415x over previous
#include <cuda_runtime.h>
#include <cstddef>
#include <cstdint>

// Problem constants (from reference)
static constexpr int B  = 4;
static constexpr int C  = 64;
static constexpr int NX = 432;
static constexpr int NY = 496;
static constexpr int NBINS = 3;
static constexpr int  PLANE   = NY * NX;            // 214272
static constexpr int  PLANE4  = PLANE / 4;          // 53568
static constexpr long PER_BIN4 = (long)B * C * PLANE4;

// Inverse index map: cell -> pillar row + 1 (0 = empty). uint16 (np<65535).
// INVARIANT: all-zero at kernel_launch entry. Zero-initialized at module
// load; the gather kernel re-zeroes every entry it found occupied, restoring
// the invariant for the next call (including graph replays).
__device__ unsigned short g_idx[NBINS * B * PLANE];

// ---------------------------------------------------------------------------
// Kernel 1: scatter (pillar row + 1) into the map. Flat grid over all
// 3*np pillars (tiny: 192K threads, one 16B coord load + one 2B store each).
// ---------------------------------------------------------------------------
__global__ void scatter_idx(const int* __restrict__ vc0,
                            const int* __restrict__ vc1,
                            const int* __restrict__ vc2, int np) {
    int t = blockIdx.x * blockDim.x + threadIdx.x;
    if (t >= NBINS * np) return;
    int bin = t / np;
    int p   = t - bin * np;
    const int* vc = (bin == 0) ? vc0 : (bin == 1) ? vc1 : vc2;
    int4 co = reinterpret_cast<const int4*>(vc)[p];  // [b, z, y, x]
    // reference flat-in-sample: z + y*NX + x (z == 0, kept for exactness)
    int cell = co.x * PLANE + co.y + co.z * NX + co.w;
    g_idx[bin * (B * PLANE) + cell] = (unsigned short)(p + 1);
}

// ---------------------------------------------------------------------------
// Kernel 2: streaming gather + self-clearing map.
// Thread owns 4 consecutive cells: one ushort4 idx load (then zeroes the
// entry if occupied). Channel loop: 4 channels/iter, one LDG.128 per
// occupied cell, register transpose, 4 coalesced float4 streaming stores.
// unroll 8 batches ~32 loads/stores per warp scheduling round — per-warp
// MLP is what saturates the HBM write stream (R6 vs R7 evidence).
// grid = (ceil(PLANE4/256), B, NBINS)
// ---------------------------------------------------------------------------
__global__ void __launch_bounds__(256, 4)
gather_out(const float* __restrict__ pf0,
           const float* __restrict__ pf1,
           const float* __restrict__ pf2,
           float* __restrict__ out) {
    const int bin = blockIdx.z;
    const float* __restrict__ pf = (bin == 0) ? pf0 : (bin == 1) ? pf1 : pf2;
    const int b = blockIdx.y;

    int s4 = blockIdx.x * blockDim.x + threadIdx.x;
    if (s4 >= PLANE4) return;

    ushort4* map4 = reinterpret_cast<ushort4*>(
        g_idx + (size_t)(bin * B + b) * PLANE);
    const ushort4 u = map4[s4];

    // Self-clear: restore the all-zero invariant for the next launch.
    if (u.x | u.y | u.z | u.w) {
        map4[s4] = make_ushort4(0, 0, 0, 0);
    }

    // Feature row base offsets ((p+1-1) * 64 channels)
    const int o0 = ((int)u.x - 1) << 6;
    const int o1 = ((int)u.y - 1) << 6;
    const int o2 = ((int)u.z - 1) << 6;
    const int o3 = ((int)u.w - 1) << 6;

    float4* dst = reinterpret_cast<float4*>(out)
                + (long)bin * PER_BIN4 + (long)b * C * PLANE4 + s4;

    const float4 z4 = make_float4(0.f, 0.f, 0.f, 0.f);

    #pragma unroll 8
    for (int c = 0; c < C; c += 4) {
        // One 16B load per occupied cell: channels c..c+3 of its feature row
        float4 r0 = u.x ? __ldg(reinterpret_cast<const float4*>(pf + o0 + c)) : z4;
        float4 r1 = u.y ? __ldg(reinterpret_cast<const float4*>(pf + o1 + c)) : z4;
        float4 r2 = u.z ? __ldg(reinterpret_cast<const float4*>(pf + o2 + c)) : z4;
        float4 r3 = u.w ? __ldg(reinterpret_cast<const float4*>(pf + o3 + c)) : z4;

        // Register transpose: channel-major stores (cells 0..3 contiguous)
        __stcs(dst + (long)(c + 0) * PLANE4, make_float4(r0.x, r1.x, r2.x, r3.x));
        __stcs(dst + (long)(c + 1) * PLANE4, make_float4(r0.y, r1.y, r2.y, r3.y));
        __stcs(dst + (long)(c + 2) * PLANE4, make_float4(r0.z, r1.z, r2.z, r3.z));
        __stcs(dst + (long)(c + 3) * PLANE4, make_float4(r0.w, r1.w, r2.w, r3.w));
    }
}

extern "C" void kernel_launch(void* const* d_in, const int* in_sizes, int n_in,
                              void* d_out, int out_size) {
    const float* pf0 = (const float*)d_in[0];
    const int*   vc0 = (const int*)  d_in[1];
    const float* pf1 = (const float*)d_in[2];
    const int*   vc1 = (const int*)  d_in[3];
    const float* pf2 = (const float*)d_in[4];
    const int*   vc2 = (const int*)  d_in[5];
    float* out = (float*)d_out;

    const int np = in_sizes[1] / 4;  // pillars per bin

    // 1) scatter pillar ids (+1) into the (all-zero) idx map
    {
        int total = NBINS * np;
        scatter_idx<<<(total + 255) / 256, 256>>>(vc0, vc1, vc2, np);
    }

    // 2) streaming gather -> output; also re-zeroes the map entries it used
    {
        dim3 grid((PLANE4 + 255) / 256, B, NBINS);
        gather_out<<<grid, 256>>>(pf0, pf1, pf2, out);
    }
}